// round 6
// baseline (speedup 1.0000x reference)
#include <cuda_runtime.h>

// ---------------------------------------------------------------------------
// Contextual attention, decomposed:
//   GEMM1: S[q,p] = <wn_q, pf_p>          (4096 x 4096 x 1152)
//   Fuse : 9-tap diagonal gather via flat transpose
//   Softmax over q (columns), scale 10, mask gate mm[q]
//   GEMM2: OP[p,m] = sum_q A[q,p] RW[q,m] (4096 x 2048 x 4096)
//   Scatter: out[c,y,x] = 0.25 * sum of <=4 OP taps
// ---------------------------------------------------------------------------

#define CDIM 128
#define HW   128
#define HD   64
#define L    4096          // HD*HD
#define KP   1152          // CDIM*9
#define MP   2048          // CDIM*16
#define BSTRIDE (CDIM*HW*HW)

typedef unsigned long long u64;

// -------------------------- device scratch --------------------------------
__device__ float g_WnT[(size_t)KP * L];          // [k][q]
__device__ float g_PfT[(size_t)KP * L];          // [k][p]
__device__ float g_RW [(size_t)L  * MP];         // [q][m]
__device__ float g_S  [(size_t)L  * L];          // [q][p]
__device__ float g_F  [(size_t)L  * L];          // [q][p] fused, then softmaxed
__device__ float g_OP [(size_t)L  * MP];         // [p][m]
__device__ float g_norm_inv[L];
__device__ float g_mm[L];
__device__ float g_pmax[32 * L];
__device__ float g_psum[32 * L];
__device__ float g_cmax[L];
__device__ float g_cinv[L];

// -------------------------- small helpers ---------------------------------
__device__ __forceinline__ int tau_idx(int a) { return ((a & 63) << 6) | (a >> 6); }

__device__ __forceinline__ u64 pack2(float lo, float hi) {
    u64 r; asm("mov.b64 %0, {%1, %2};" : "=l"(r) : "f"(lo), "f"(hi)); return r;
}
__device__ __forceinline__ float2 unpack2(u64 v) {
    float2 r; asm("mov.b64 {%0, %1}, %2;" : "=f"(r.x), "=f"(r.y) : "l"(v)); return r;
}
__device__ __forceinline__ void fma2(u64& d, u64 a, u64 b) {
    asm("fma.rn.f32x2 %0, %1, %2, %0;" : "+l"(d) : "l"(a), "l"(b));
}

// -------------------------- mask gate --------------------------------------
__global__ void k_mm(const float* __restrict__ mask) {
    int q = blockIdx.x * blockDim.x + threadIdx.x;
    if (q >= L) return;
    int qy = q >> 6, qx = q & 63;
    float s = 0.f;
    for (int dy = -1; dy <= 1; dy++)
        for (int dx = -1; dx <= 1; dx++) {
            int yy = qy + dy, xx = qx + dx;
            if ((unsigned)yy < HD && (unsigned)xx < HD)
                s += mask[(2 * yy) * HW + 2 * xx];
        }
    g_mm[q] = (s == 0.0f) ? 1.0f : 0.0f;
}

// -------------------------- patch norms ------------------------------------
__global__ void k_norm(const float* __restrict__ b) {
    int q = blockIdx.x;
    int c = threadIdx.x;                 // 128 threads
    int qy = q >> 6, qx = q & 63;
    const float* bc = b + (size_t)c * HW * HW;
    float s = 0.f;
    for (int dy = -1; dy <= 1; dy++) {
        int yy = qy + dy; if ((unsigned)yy >= HD) continue;
        for (int dx = -1; dx <= 1; dx++) {
            int xx = qx + dx; if ((unsigned)xx >= HD) continue;
            float v = bc[(2 * yy) * HW + 2 * xx];
            s += v * v;
        }
    }
    __shared__ float sh[128];
    sh[c] = s; __syncthreads();
    for (int o = 64; o > 0; o >>= 1) {
        if (c < o) sh[c] += sh[c + o];
        __syncthreads();
    }
    if (c == 0) {
        float n = sqrtf(sh[0]);
        g_norm_inv[q] = 1.0f / fmaxf(n, 1e-4f);
    }
}

// -------------------- build PfT (f patches) & WnT (normalized b patches) ---
__global__ void k_build(const float* __restrict__ f, const float* __restrict__ b) {
    int idx = blockIdx.x * blockDim.x + threadIdx.x;
    if (idx >= KP * L) return;
    int q = idx & (L - 1);
    int k = idx >> 12;
    int c = k / 9;
    int r = k - 9 * c;
    int dy = r / 3 - 1, dx = r % 3 - 1;
    int qy = (q >> 6) + dy, qx = (q & 63) + dx;
    float fv = 0.f, bv = 0.f;
    if ((unsigned)qy < HD && (unsigned)qx < HD) {
        size_t off = (size_t)c * HW * HW + (size_t)(2 * qy) * HW + 2 * qx;
        fv = f[off]; bv = b[off];
    }
    g_PfT[idx] = fv;
    g_WnT[idx] = bv * g_norm_inv[q];
}

// -------------------- build RW (raw 4x4 stride-2 patches of full-res b) ----
__global__ void k_buildRW(const float* __restrict__ b) {
    size_t idx = (size_t)blockIdx.x * blockDim.x + threadIdx.x;
    if (idx >= (size_t)L * MP) return;
    int m = (int)(idx & (MP - 1));
    int q = (int)(idx >> 11);
    int c = m >> 4, i = (m >> 2) & 3, j = m & 3;
    int y = 2 * (q >> 6) - 1 + i;
    int x = 2 * (q & 63) - 1 + j;
    float v = 0.f;
    if ((unsigned)y < HW && (unsigned)x < HW)
        v = b[(size_t)c * HW * HW + (size_t)y * HW + x];
    g_RW[idx] = v;
}

// -------------------------- SGEMM (TN, fp32x2 FFMA2) -----------------------
// C[M,N] = sum_k A[k][m] * B[k][n];  BM=BN=128, BK=8, 256 thr, 8x8 microtile
__global__ __launch_bounds__(256) void k_gemm(int which) {
    const float* __restrict__ A;
    const float* __restrict__ B;
    float* __restrict__ C;
    int N, K;
    if (which == 0) { A = g_WnT; B = g_PfT; C = g_S;  N = L;  K = KP; }
    else            { A = g_F;   B = g_RW;  C = g_OP; N = MP; K = L;  }
    const int M = L;

    __shared__ __align__(16) float As[8][128];
    __shared__ __align__(16) float Bs[8][128];

    int bm = blockIdx.y * 128, bn = blockIdx.x * 128;
    int tid = threadIdx.x;
    int lr = tid >> 5;
    int lc = (tid & 31) << 2;
    int tm = (tid >> 4) << 3;
    int tn = (tid & 15) << 3;

    const float* Ag = A + (size_t)lr * M + bm + lc;
    const float* Bg = B + (size_t)lr * N + bn + lc;
    float4 ra = *(const float4*)Ag;
    float4 rb = *(const float4*)Bg;

    u64 acc2[8][4];
#pragma unroll
    for (int i = 0; i < 8; i++)
#pragma unroll
        for (int j = 0; j < 4; j++) acc2[i][j] = 0ull;

    int kiter = K >> 3;
    for (int t = 0; t < kiter; t++) {
        *(float4*)&As[lr][lc] = ra;
        *(float4*)&Bs[lr][lc] = rb;
        __syncthreads();
        if (t + 1 < kiter) {
            Ag += 8 * (size_t)M; Bg += 8 * (size_t)N;
            ra = *(const float4*)Ag;
            rb = *(const float4*)Bg;
        }
#pragma unroll
        for (int kk = 0; kk < 8; kk++) {
            float4 a0 = *(const float4*)&As[kk][tm];
            float4 a1 = *(const float4*)&As[kk][tm + 4];
            float4 b0 = *(const float4*)&Bs[kk][tn];
            float4 b1 = *(const float4*)&Bs[kk][tn + 4];
            u64 bv0 = pack2(b0.x, b0.y), bv1 = pack2(b0.z, b0.w);
            u64 bv2 = pack2(b1.x, b1.y), bv3 = pack2(b1.z, b1.w);
            float av[8] = {a0.x, a0.y, a0.z, a0.w, a1.x, a1.y, a1.z, a1.w};
#pragma unroll
            for (int i = 0; i < 8; i++) {
                u64 aa = pack2(av[i], av[i]);
                fma2(acc2[i][0], aa, bv0);
                fma2(acc2[i][1], aa, bv1);
                fma2(acc2[i][2], aa, bv2);
                fma2(acc2[i][3], aa, bv3);
            }
        }
        __syncthreads();
    }

#pragma unroll
    for (int i = 0; i < 8; i++) {
        float2 v0 = unpack2(acc2[i][0]);
        float2 v1 = unpack2(acc2[i][1]);
        float2 v2 = unpack2(acc2[i][2]);
        float2 v3 = unpack2(acc2[i][3]);
        float4 o0 = make_float4(v0.x, v0.y, v1.x, v1.y);
        float4 o1 = make_float4(v2.x, v2.y, v3.x, v3.y);
        size_t row = (size_t)(bm + tm + i) * N + (bn + tn);
        *(float4*)&C[row]     = o0;
        *(float4*)&C[row + 4] = o1;
    }
}

// -------------------------- fuse (two eye(3) convs + transposes) -----------
__global__ void k_fuse() {
    int idx = blockIdx.x * blockDim.x + threadIdx.x;   // < L*L = 16.7M
    int p = idx & (L - 1);
    int q = idx >> 12;
    int tq = tau_idx(q), tp = tau_idx(p);
    float acc = 0.f;
#pragma unroll
    for (int d2 = -1; d2 <= 1; d2++) {
        int aq = tq + d2, ap = tp + d2;
        if ((unsigned)aq < L && (unsigned)ap < L) {
            int uq = tau_idx(aq), up = tau_idx(ap);
#pragma unroll
            for (int d1 = -1; d1 <= 1; d1++) {
                int vq = uq + d1, vp = up + d1;
                if ((unsigned)vq < L && (unsigned)vp < L)
                    acc += g_S[(size_t)vq * L + vp];
            }
        }
    }
    g_F[(size_t)q * L + p] = acc;
}

// -------------------------- softmax over q (split along q) -----------------
__global__ void k_smax_max() {
    int p = blockIdx.x * blockDim.x + threadIdx.x;     // grid.x = 16
    int q0 = blockIdx.y * 128;                          // grid.y = 32
    float m = -1e30f;
#pragma unroll 4
    for (int q = q0; q < q0 + 128; q++) {
        float v = g_F[(size_t)q * L + p] * g_mm[q] * 10.0f;
        m = fmaxf(m, v);
    }
    g_pmax[blockIdx.y * L + p] = m;
}
__global__ void k_rmax() {
    int p = blockIdx.x * blockDim.x + threadIdx.x;
    float m = -1e30f;
#pragma unroll
    for (int i = 0; i < 32; i++) m = fmaxf(m, g_pmax[i * L + p]);
    g_cmax[p] = m;
}
__global__ void k_smax_sum() {
    int p = blockIdx.x * blockDim.x + threadIdx.x;
    int q0 = blockIdx.y * 128;
    float m = g_cmax[p];
    float s = 0.f;
#pragma unroll 4
    for (int q = q0; q < q0 + 128; q++) {
        float v = g_F[(size_t)q * L + p] * g_mm[q] * 10.0f;
        float e = expf(v - m);
        s += e;
        g_F[(size_t)q * L + p] = e;
    }
    g_psum[blockIdx.y * L + p] = s;
}
__global__ void k_rsum() {
    int p = blockIdx.x * blockDim.x + threadIdx.x;
    float s = 0.f;
#pragma unroll
    for (int i = 0; i < 32; i++) s += g_psum[i * L + p];
    g_cinv[p] = 1.0f / s;
}
__global__ void k_smax_norm() {
    int idx = blockIdx.x * blockDim.x + threadIdx.x;
    int p = idx & (L - 1);
    int q = idx >> 12;
    g_F[(size_t)q * L + p] = g_F[(size_t)q * L + p] * g_mm[q] * g_cinv[p];
}

// -------------------------- final scatter ----------------------------------
__global__ void k_scatter(float* __restrict__ out) {
    int idx = blockIdx.x * blockDim.x + threadIdx.x;   // < CDIM*HW*HW
    int c = idx >> 14;
    int y = (idx >> 7) & 127;
    int x = idx & 127;
    int py1 = (y + 1) >> 1;
    int px1 = (x + 1) >> 1;
    float acc = 0.f;
#pragma unroll
    for (int t = 0; t < 2; t++) {
        int py = py1 - t;
        if ((unsigned)py >= 64) continue;
        int i = y + 1 - 2 * py;     // in [0,4)
#pragma unroll
        for (int s2 = 0; s2 < 2; s2++) {
            int px = px1 - s2;
            if ((unsigned)px >= 64) continue;
            int j = x + 1 - 2 * px;
            acc += g_OP[(size_t)(py * 64 + px) * MP + c * 16 + i * 4 + j];
        }
    }
    out[idx] = acc * 0.25f;
}

// -------------------------- launch ------------------------------------------
extern "C" void kernel_launch(void* const* d_in, const int* in_sizes, int n_in,
                              void* d_out, int out_size) {
    (void)in_sizes; (void)n_in; (void)out_size;
    const float* f    = (const float*)d_in[0];
    const float* b    = (const float*)d_in[1];
    const float* mask = (const float*)d_in[2];
    float* out = (float*)d_out;

    k_mm<<<16, 256>>>(mask);

    for (int bi = 0; bi < 2; bi++) {
        const float* fb = f + (size_t)bi * BSTRIDE;
        const float* bb = b + (size_t)bi * BSTRIDE;

        k_norm<<<L, 128>>>(bb);
        k_build<<<(KP * L) / 256, 256>>>(fb, bb);
        k_buildRW<<<(int)(((size_t)L * MP) / 256), 256>>>(bb);

        k_gemm<<<dim3(L / 128, L / 128), 256>>>(0);       // S = WnT^T PfT

        k_fuse<<<(int)(((size_t)L * L) / 256), 256>>>();

        k_smax_max<<<dim3(L / 256, 32), 256>>>();
        k_rmax<<<L / 256, 256>>>();
        k_smax_sum<<<dim3(L / 256, 32), 256>>>();
        k_rsum<<<L / 256, 256>>>();
        k_smax_norm<<<(int)(((size_t)L * L) / 256), 256>>>();

        k_gemm<<<dim3(MP / 128, L / 128), 256>>>(1);      // OP = A^T RW

        k_scatter<<<(CDIM * HW * HW) / 256, 256>>>(out + (size_t)bi * BSTRIDE);
    }
}

// round 7
// speedup vs baseline: 1.0021x; 1.0021x over previous
#include <cuda_runtime.h>

// ---------------------------------------------------------------------------
// Contextual attention, decomposed:
//   GEMM1: S[q,p] = <wn_q, pf_p>          (4096 x 4096 x 1152)
//   Fuse : 9-tap diagonal gather via flat transpose
//   Softmax over q (columns), scale 10, mask gate mm[q]
//   GEMM2: OP[p,m] = sum_q A[q,p] RW[q,m] (4096 x 2048 x 4096)
//   Scatter: out[c,y,x] = 0.25 * sum of <=4 OP taps
// ---------------------------------------------------------------------------

#define CDIM 128
#define HW   128
#define HD   64
#define L    4096          // HD*HD
#define KP   1152          // CDIM*9
#define MP   2048          // CDIM*16
#define BSTRIDE (CDIM*HW*HW)

typedef unsigned long long u64;

// -------------------------- device scratch --------------------------------
__device__ float g_WnT[(size_t)KP * L];          // [k][q]
__device__ float g_PfT[(size_t)KP * L];          // [k][p]
__device__ float g_RW [(size_t)L  * MP];         // [q][m]
__device__ float g_S  [(size_t)L  * L];          // [q][p]
__device__ float g_F  [(size_t)L  * L];          // [q][p] fused, then softmaxed
__device__ float g_OP [(size_t)L  * MP];         // [p][m]
__device__ float g_norm_inv[L];
__device__ float g_mm[L];
__device__ float g_pmax[32 * L];
__device__ float g_psum[32 * L];
__device__ float g_cmax[L];
__device__ float g_cinv[L];

// -------------------------- small helpers ---------------------------------
__device__ __forceinline__ int tau_idx(int a) { return ((a & 63) << 6) | (a >> 6); }

__device__ __forceinline__ u64 pack2(float lo, float hi) {
    u64 r; asm("mov.b64 %0, {%1, %2};" : "=l"(r) : "f"(lo), "f"(hi)); return r;
}
__device__ __forceinline__ float2 unpack2(u64 v) {
    float2 r; asm("mov.b64 {%0, %1}, %2;" : "=f"(r.x), "=f"(r.y) : "l"(v)); return r;
}
__device__ __forceinline__ void fma2(u64& d, u64 a, u64 b) {
    asm("fma.rn.f32x2 %0, %1, %2, %0;" : "+l"(d) : "l"(a), "l"(b));
}

// -------------------------- mask gate --------------------------------------
__global__ void k_mm(const float* __restrict__ mask) {
    int q = blockIdx.x * blockDim.x + threadIdx.x;
    if (q >= L) return;
    int qy = q >> 6, qx = q & 63;
    float s = 0.f;
    for (int dy = -1; dy <= 1; dy++)
        for (int dx = -1; dx <= 1; dx++) {
            int yy = qy + dy, xx = qx + dx;
            if ((unsigned)yy < HD && (unsigned)xx < HD)
                s += mask[(2 * yy) * HW + 2 * xx];
        }
    g_mm[q] = (s == 0.0f) ? 1.0f : 0.0f;
}

// -------------------------- patch norms ------------------------------------
__global__ void k_norm(const float* __restrict__ b) {
    int q = blockIdx.x;
    int c = threadIdx.x;                 // 128 threads
    int qy = q >> 6, qx = q & 63;
    const float* bc = b + (size_t)c * HW * HW;
    float s = 0.f;
    for (int dy = -1; dy <= 1; dy++) {
        int yy = qy + dy; if ((unsigned)yy >= HD) continue;
        for (int dx = -1; dx <= 1; dx++) {
            int xx = qx + dx; if ((unsigned)xx >= HD) continue;
            float v = bc[(2 * yy) * HW + 2 * xx];
            s += v * v;
        }
    }
    __shared__ float sh[128];
    sh[c] = s; __syncthreads();
    for (int o = 64; o > 0; o >>= 1) {
        if (c < o) sh[c] += sh[c + o];
        __syncthreads();
    }
    if (c == 0) {
        float n = sqrtf(sh[0]);
        g_norm_inv[q] = 1.0f / fmaxf(n, 1e-4f);
    }
}

// -------------------- build PfT (f patches) & WnT (normalized b patches) ---
__global__ void k_build(const float* __restrict__ f, const float* __restrict__ b) {
    int idx = blockIdx.x * blockDim.x + threadIdx.x;
    if (idx >= KP * L) return;
    int q = idx & (L - 1);
    int k = idx >> 12;
    int c = k / 9;
    int r = k - 9 * c;
    int dy = r / 3 - 1, dx = r % 3 - 1;
    int qy = (q >> 6) + dy, qx = (q & 63) + dx;
    float fv = 0.f, bv = 0.f;
    if ((unsigned)qy < HD && (unsigned)qx < HD) {
        size_t off = (size_t)c * HW * HW + (size_t)(2 * qy) * HW + 2 * qx;
        fv = f[off]; bv = b[off];
    }
    g_PfT[idx] = fv;
    g_WnT[idx] = bv * g_norm_inv[q];
}

// -------------------- build RW (raw 4x4 stride-2 patches of full-res b) ----
__global__ void k_buildRW(const float* __restrict__ b) {
    size_t idx = (size_t)blockIdx.x * blockDim.x + threadIdx.x;
    if (idx >= (size_t)L * MP) return;
    int m = (int)(idx & (MP - 1));
    int q = (int)(idx >> 11);
    int c = m >> 4, i = (m >> 2) & 3, j = m & 3;
    int y = 2 * (q >> 6) - 1 + i;
    int x = 2 * (q & 63) - 1 + j;
    float v = 0.f;
    if ((unsigned)y < HW && (unsigned)x < HW)
        v = b[(size_t)c * HW * HW + (size_t)y * HW + x];
    g_RW[idx] = v;
}

// -------------------------- SGEMM (TN, fp32x2 FFMA2) -----------------------
// C[M,N] = sum_k A[k][m] * B[k][n];  BM=BN=128, BK=8, 256 thr, 8x8 microtile
__global__ __launch_bounds__(256) void k_gemm(int which) {
    const float* __restrict__ A;
    const float* __restrict__ B;
    float* __restrict__ C;
    int N, K;
    if (which == 0) { A = g_WnT; B = g_PfT; C = g_S;  N = L;  K = KP; }
    else            { A = g_F;   B = g_RW;  C = g_OP; N = MP; K = L;  }
    const int M = L;

    __shared__ __align__(16) float As[8][128];
    __shared__ __align__(16) float Bs[8][128];

    int bm = blockIdx.y * 128, bn = blockIdx.x * 128;
    int tid = threadIdx.x;
    int lr = tid >> 5;
    int lc = (tid & 31) << 2;
    int tm = (tid >> 4) << 3;
    int tn = (tid & 15) << 3;

    const float* Ag = A + (size_t)lr * M + bm + lc;
    const float* Bg = B + (size_t)lr * N + bn + lc;
    float4 ra = *(const float4*)Ag;
    float4 rb = *(const float4*)Bg;

    u64 acc2[8][4];
#pragma unroll
    for (int i = 0; i < 8; i++)
#pragma unroll
        for (int j = 0; j < 4; j++) acc2[i][j] = 0ull;

    int kiter = K >> 3;
    for (int t = 0; t < kiter; t++) {
        *(float4*)&As[lr][lc] = ra;
        *(float4*)&Bs[lr][lc] = rb;
        __syncthreads();
        if (t + 1 < kiter) {
            Ag += 8 * (size_t)M; Bg += 8 * (size_t)N;
            ra = *(const float4*)Ag;
            rb = *(const float4*)Bg;
        }
#pragma unroll
        for (int kk = 0; kk < 8; kk++) {
            float4 a0 = *(const float4*)&As[kk][tm];
            float4 a1 = *(const float4*)&As[kk][tm + 4];
            float4 b0 = *(const float4*)&Bs[kk][tn];
            float4 b1 = *(const float4*)&Bs[kk][tn + 4];
            u64 bv0 = pack2(b0.x, b0.y), bv1 = pack2(b0.z, b0.w);
            u64 bv2 = pack2(b1.x, b1.y), bv3 = pack2(b1.z, b1.w);
            float av[8] = {a0.x, a0.y, a0.z, a0.w, a1.x, a1.y, a1.z, a1.w};
#pragma unroll
            for (int i = 0; i < 8; i++) {
                u64 aa = pack2(av[i], av[i]);
                fma2(acc2[i][0], aa, bv0);
                fma2(acc2[i][1], aa, bv1);
                fma2(acc2[i][2], aa, bv2);
                fma2(acc2[i][3], aa, bv3);
            }
        }
        __syncthreads();
    }

#pragma unroll
    for (int i = 0; i < 8; i++) {
        float2 v0 = unpack2(acc2[i][0]);
        float2 v1 = unpack2(acc2[i][1]);
        float2 v2 = unpack2(acc2[i][2]);
        float2 v3 = unpack2(acc2[i][3]);
        float4 o0 = make_float4(v0.x, v0.y, v1.x, v1.y);
        float4 o1 = make_float4(v2.x, v2.y, v3.x, v3.y);
        size_t row = (size_t)(bm + tm + i) * N + (bn + tn);
        *(float4*)&C[row]     = o0;
        *(float4*)&C[row + 4] = o1;
    }
}

// -------------------------- fuse (two eye(3) convs + transposes) -----------
__global__ void k_fuse() {
    int idx = blockIdx.x * blockDim.x + threadIdx.x;   // < L*L = 16.7M
    int p = idx & (L - 1);
    int q = idx >> 12;
    int tq = tau_idx(q), tp = tau_idx(p);
    float acc = 0.f;
#pragma unroll
    for (int d2 = -1; d2 <= 1; d2++) {
        int aq = tq + d2, ap = tp + d2;
        if ((unsigned)aq < L && (unsigned)ap < L) {
            int uq = tau_idx(aq), up = tau_idx(ap);
#pragma unroll
            for (int d1 = -1; d1 <= 1; d1++) {
                int vq = uq + d1, vp = up + d1;
                if ((unsigned)vq < L && (unsigned)vp < L)
                    acc += g_S[(size_t)vq * L + vp];
            }
        }
    }
    g_F[(size_t)q * L + p] = acc;
}

// -------------------------- softmax over q (split along q) -----------------
__global__ void k_smax_max() {
    int p = blockIdx.x * blockDim.x + threadIdx.x;     // grid.x = 16
    int q0 = blockIdx.y * 128;                          // grid.y = 32
    float m = -1e30f;
#pragma unroll 4
    for (int q = q0; q < q0 + 128; q++) {
        float v = g_F[(size_t)q * L + p] * g_mm[q] * 10.0f;
        m = fmaxf(m, v);
    }
    g_pmax[blockIdx.y * L + p] = m;
}
__global__ void k_rmax() {
    int p = blockIdx.x * blockDim.x + threadIdx.x;
    float m = -1e30f;
#pragma unroll
    for (int i = 0; i < 32; i++) m = fmaxf(m, g_pmax[i * L + p]);
    g_cmax[p] = m;
}
__global__ void k_smax_sum() {
    int p = blockIdx.x * blockDim.x + threadIdx.x;
    int q0 = blockIdx.y * 128;
    float m = g_cmax[p];
    float s = 0.f;
#pragma unroll 4
    for (int q = q0; q < q0 + 128; q++) {
        float v = g_F[(size_t)q * L + p] * g_mm[q] * 10.0f;
        float e = expf(v - m);
        s += e;
        g_F[(size_t)q * L + p] = e;
    }
    g_psum[blockIdx.y * L + p] = s;
}
__global__ void k_rsum() {
    int p = blockIdx.x * blockDim.x + threadIdx.x;
    float s = 0.f;
#pragma unroll
    for (int i = 0; i < 32; i++) s += g_psum[i * L + p];
    g_cinv[p] = 1.0f / s;
}
__global__ void k_smax_norm() {
    int idx = blockIdx.x * blockDim.x + threadIdx.x;
    int p = idx & (L - 1);
    int q = idx >> 12;
    g_F[(size_t)q * L + p] = g_F[(size_t)q * L + p] * g_mm[q] * g_cinv[p];
}

// -------------------------- final scatter ----------------------------------
__global__ void k_scatter(float* __restrict__ out) {
    int idx = blockIdx.x * blockDim.x + threadIdx.x;   // < CDIM*HW*HW
    int c = idx >> 14;
    int y = (idx >> 7) & 127;
    int x = idx & 127;
    int py1 = (y + 1) >> 1;
    int px1 = (x + 1) >> 1;
    float acc = 0.f;
#pragma unroll
    for (int t = 0; t < 2; t++) {
        int py = py1 - t;
        if ((unsigned)py >= 64) continue;
        int i = y + 1 - 2 * py;     // in [0,4)
#pragma unroll
        for (int s2 = 0; s2 < 2; s2++) {
            int px = px1 - s2;
            if ((unsigned)px >= 64) continue;
            int j = x + 1 - 2 * px;
            acc += g_OP[(size_t)(py * 64 + px) * MP + c * 16 + i * 4 + j];
        }
    }
    out[idx] = acc * 0.25f;
}

// -------------------------- launch ------------------------------------------
extern "C" void kernel_launch(void* const* d_in, const int* in_sizes, int n_in,
                              void* d_out, int out_size) {
    (void)in_sizes; (void)n_in; (void)out_size;
    const float* f    = (const float*)d_in[0];
    const float* b    = (const float*)d_in[1];
    const float* mask = (const float*)d_in[2];
    float* out = (float*)d_out;

    k_mm<<<16, 256>>>(mask);

    for (int bi = 0; bi < 2; bi++) {
        const float* fb = f + (size_t)bi * BSTRIDE;
        const float* bb = b + (size_t)bi * BSTRIDE;

        k_norm<<<L, 128>>>(bb);
        k_build<<<(KP * L) / 256, 256>>>(fb, bb);
        k_buildRW<<<(int)(((size_t)L * MP) / 256), 256>>>(bb);

        k_gemm<<<dim3(L / 128, L / 128), 256>>>(0);       // S = WnT^T PfT

        k_fuse<<<(int)(((size_t)L * L) / 256), 256>>>();

        k_smax_max<<<dim3(L / 256, 32), 256>>>();
        k_rmax<<<L / 256, 256>>>();
        k_smax_sum<<<dim3(L / 256, 32), 256>>>();
        k_rsum<<<L / 256, 256>>>();
        k_smax_norm<<<(int)(((size_t)L * L) / 256), 256>>>();

        k_gemm<<<dim3(MP / 128, L / 128), 256>>>(1);      // OP = A^T RW

        k_scatter<<<(CDIM * HW * HW) / 256, 256>>>(out + (size_t)bi * BSTRIDE);
    }
}

// round 8
// speedup vs baseline: 1.0028x; 1.0007x over previous
#include <cuda_runtime.h>

// ---------------------------------------------------------------------------
// Contextual attention, decomposed:
//   GEMM1: S[q,p] = <wn_q, pf_p>          (4096 x 4096 x 1152)
//   Fuse : 9-tap diagonal gather via flat transpose
//   Softmax over q (columns), scale 10, mask gate mm[q]
//   GEMM2: OP[p,m] = sum_q A[q,p] RW[q,m] (4096 x 2048 x 4096)
//   Scatter: out[c,y,x] = 0.25 * sum of <=4 OP taps
// ---------------------------------------------------------------------------

#define CDIM 128
#define HW   128
#define HD   64
#define L    4096          // HD*HD
#define KP   1152          // CDIM*9
#define MP   2048          // CDIM*16
#define BSTRIDE (CDIM*HW*HW)

typedef unsigned long long u64;

// -------------------------- device scratch --------------------------------
__device__ float g_WnT[(size_t)KP * L];          // [k][q]
__device__ float g_PfT[(size_t)KP * L];          // [k][p]
__device__ float g_RW [(size_t)L  * MP];         // [q][m]
__device__ float g_S  [(size_t)L  * L];          // [q][p]
__device__ float g_F  [(size_t)L  * L];          // [q][p] fused, then softmaxed
__device__ float g_OP [(size_t)L  * MP];         // [p][m]
__device__ float g_norm_inv[L];
__device__ float g_mm[L];
__device__ float g_pmax[32 * L];
__device__ float g_psum[32 * L];
__device__ float g_cmax[L];
__device__ float g_cinv[L];

// -------------------------- small helpers ---------------------------------
__device__ __forceinline__ int tau_idx(int a) { return ((a & 63) << 6) | (a >> 6); }

__device__ __forceinline__ u64 pack2(float lo, float hi) {
    u64 r; asm("mov.b64 %0, {%1, %2};" : "=l"(r) : "f"(lo), "f"(hi)); return r;
}
__device__ __forceinline__ float2 unpack2(u64 v) {
    float2 r; asm("mov.b64 {%0, %1}, %2;" : "=f"(r.x), "=f"(r.y) : "l"(v)); return r;
}
__device__ __forceinline__ void fma2(u64& d, u64 a, u64 b) {
    asm("fma.rn.f32x2 %0, %1, %2, %0;" : "+l"(d) : "l"(a), "l"(b));
}

// -------------------------- mask gate --------------------------------------
__global__ void k_mm(const float* __restrict__ mask) {
    int q = blockIdx.x * blockDim.x + threadIdx.x;
    if (q >= L) return;
    int qy = q >> 6, qx = q & 63;
    float s = 0.f;
    for (int dy = -1; dy <= 1; dy++)
        for (int dx = -1; dx <= 1; dx++) {
            int yy = qy + dy, xx = qx + dx;
            if ((unsigned)yy < HD && (unsigned)xx < HD)
                s += mask[(2 * yy) * HW + 2 * xx];
        }
    g_mm[q] = (s == 0.0f) ? 1.0f : 0.0f;
}

// -------------------------- patch norms ------------------------------------
__global__ void k_norm(const float* __restrict__ b) {
    int q = blockIdx.x;
    int c = threadIdx.x;                 // 128 threads
    int qy = q >> 6, qx = q & 63;
    const float* bc = b + (size_t)c * HW * HW;
    float s = 0.f;
    for (int dy = -1; dy <= 1; dy++) {
        int yy = qy + dy; if ((unsigned)yy >= HD) continue;
        for (int dx = -1; dx <= 1; dx++) {
            int xx = qx + dx; if ((unsigned)xx >= HD) continue;
            float v = bc[(2 * yy) * HW + 2 * xx];
            s += v * v;
        }
    }
    __shared__ float sh[128];
    sh[c] = s; __syncthreads();
    for (int o = 64; o > 0; o >>= 1) {
        if (c < o) sh[c] += sh[c + o];
        __syncthreads();
    }
    if (c == 0) {
        float n = sqrtf(sh[0]);
        g_norm_inv[q] = 1.0f / fmaxf(n, 1e-4f);
    }
}

// -------------------- build PfT (f patches) & WnT (normalized b patches) ---
__global__ void k_build(const float* __restrict__ f, const float* __restrict__ b) {
    int idx = blockIdx.x * blockDim.x + threadIdx.x;
    if (idx >= KP * L) return;
    int q = idx & (L - 1);
    int k = idx >> 12;
    int c = k / 9;
    int r = k - 9 * c;
    int dy = r / 3 - 1, dx = r % 3 - 1;
    int qy = (q >> 6) + dy, qx = (q & 63) + dx;
    float fv = 0.f, bv = 0.f;
    if ((unsigned)qy < HD && (unsigned)qx < HD) {
        size_t off = (size_t)c * HW * HW + (size_t)(2 * qy) * HW + 2 * qx;
        fv = f[off]; bv = b[off];
    }
    g_PfT[idx] = fv;
    g_WnT[idx] = bv * g_norm_inv[q];
}

// -------------------- build RW (raw 4x4 stride-2 patches of full-res b) ----
__global__ void k_buildRW(const float* __restrict__ b) {
    size_t idx = (size_t)blockIdx.x * blockDim.x + threadIdx.x;
    if (idx >= (size_t)L * MP) return;
    int m = (int)(idx & (MP - 1));
    int q = (int)(idx >> 11);
    int c = m >> 4, i = (m >> 2) & 3, j = m & 3;
    int y = 2 * (q >> 6) - 1 + i;
    int x = 2 * (q & 63) - 1 + j;
    float v = 0.f;
    if ((unsigned)y < HW && (unsigned)x < HW)
        v = b[(size_t)c * HW * HW + (size_t)y * HW + x];
    g_RW[idx] = v;
}

// -------------------------- SGEMM (TN, fp32x2 FFMA2) -----------------------
// C[M,N] = sum_k A[k][m] * B[k][n];  BM=BN=128, BK=8, 256 thr, 8x8 microtile
__global__ __launch_bounds__(256) void k_gemm(int which) {
    const float* __restrict__ A;
    const float* __restrict__ B;
    float* __restrict__ C;
    int N, K;
    if (which == 0) { A = g_WnT; B = g_PfT; C = g_S;  N = L;  K = KP; }
    else            { A = g_F;   B = g_RW;  C = g_OP; N = MP; K = L;  }
    const int M = L;

    __shared__ __align__(16) float As[8][128];
    __shared__ __align__(16) float Bs[8][128];

    int bm = blockIdx.y * 128, bn = blockIdx.x * 128;
    int tid = threadIdx.x;
    int lr = tid >> 5;
    int lc = (tid & 31) << 2;
    int tm = (tid >> 4) << 3;
    int tn = (tid & 15) << 3;

    const float* Ag = A + (size_t)lr * M + bm + lc;
    const float* Bg = B + (size_t)lr * N + bn + lc;
    float4 ra = *(const float4*)Ag;
    float4 rb = *(const float4*)Bg;

    u64 acc2[8][4];
#pragma unroll
    for (int i = 0; i < 8; i++)
#pragma unroll
        for (int j = 0; j < 4; j++) acc2[i][j] = 0ull;

    int kiter = K >> 3;
    for (int t = 0; t < kiter; t++) {
        *(float4*)&As[lr][lc] = ra;
        *(float4*)&Bs[lr][lc] = rb;
        __syncthreads();
        if (t + 1 < kiter) {
            Ag += 8 * (size_t)M; Bg += 8 * (size_t)N;
            ra = *(const float4*)Ag;
            rb = *(const float4*)Bg;
        }
#pragma unroll
        for (int kk = 0; kk < 8; kk++) {
            float4 a0 = *(const float4*)&As[kk][tm];
            float4 a1 = *(const float4*)&As[kk][tm + 4];
            float4 b0 = *(const float4*)&Bs[kk][tn];
            float4 b1 = *(const float4*)&Bs[kk][tn + 4];
            u64 bv0 = pack2(b0.x, b0.y), bv1 = pack2(b0.z, b0.w);
            u64 bv2 = pack2(b1.x, b1.y), bv3 = pack2(b1.z, b1.w);
            float av[8] = {a0.x, a0.y, a0.z, a0.w, a1.x, a1.y, a1.z, a1.w};
#pragma unroll
            for (int i = 0; i < 8; i++) {
                u64 aa = pack2(av[i], av[i]);
                fma2(acc2[i][0], aa, bv0);
                fma2(acc2[i][1], aa, bv1);
                fma2(acc2[i][2], aa, bv2);
                fma2(acc2[i][3], aa, bv3);
            }
        }
        __syncthreads();
    }

#pragma unroll
    for (int i = 0; i < 8; i++) {
        float2 v0 = unpack2(acc2[i][0]);
        float2 v1 = unpack2(acc2[i][1]);
        float2 v2 = unpack2(acc2[i][2]);
        float2 v3 = unpack2(acc2[i][3]);
        float4 o0 = make_float4(v0.x, v0.y, v1.x, v1.y);
        float4 o1 = make_float4(v2.x, v2.y, v3.x, v3.y);
        size_t row = (size_t)(bm + tm + i) * N + (bn + tn);
        *(float4*)&C[row]     = o0;
        *(float4*)&C[row + 4] = o1;
    }
}

// -------------------------- fuse (two eye(3) convs + transposes) -----------
__global__ void k_fuse() {
    int idx = blockIdx.x * blockDim.x + threadIdx.x;   // < L*L = 16.7M
    int p = idx & (L - 1);
    int q = idx >> 12;
    int tq = tau_idx(q), tp = tau_idx(p);
    float acc = 0.f;
#pragma unroll
    for (int d2 = -1; d2 <= 1; d2++) {
        int aq = tq + d2, ap = tp + d2;
        if ((unsigned)aq < L && (unsigned)ap < L) {
            int uq = tau_idx(aq), up = tau_idx(ap);
#pragma unroll
            for (int d1 = -1; d1 <= 1; d1++) {
                int vq = uq + d1, vp = up + d1;
                if ((unsigned)vq < L && (unsigned)vp < L)
                    acc += g_S[(size_t)vq * L + vp];
            }
        }
    }
    g_F[(size_t)q * L + p] = acc;
}

// -------------------------- softmax over q (split along q) -----------------
__global__ void k_smax_max() {
    int p = blockIdx.x * blockDim.x + threadIdx.x;     // grid.x = 16
    int q0 = blockIdx.y * 128;                          // grid.y = 32
    float m = -1e30f;
#pragma unroll 4
    for (int q = q0; q < q0 + 128; q++) {
        float v = g_F[(size_t)q * L + p] * g_mm[q] * 10.0f;
        m = fmaxf(m, v);
    }
    g_pmax[blockIdx.y * L + p] = m;
}
__global__ void k_rmax() {
    int p = blockIdx.x * blockDim.x + threadIdx.x;
    float m = -1e30f;
#pragma unroll
    for (int i = 0; i < 32; i++) m = fmaxf(m, g_pmax[i * L + p]);
    g_cmax[p] = m;
}
__global__ void k_smax_sum() {
    int p = blockIdx.x * blockDim.x + threadIdx.x;
    int q0 = blockIdx.y * 128;
    float m = g_cmax[p];
    float s = 0.f;
#pragma unroll 4
    for (int q = q0; q < q0 + 128; q++) {
        float v = g_F[(size_t)q * L + p] * g_mm[q] * 10.0f;
        float e = expf(v - m);
        s += e;
        g_F[(size_t)q * L + p] = e;
    }
    g_psum[blockIdx.y * L + p] = s;
}
__global__ void k_rsum() {
    int p = blockIdx.x * blockDim.x + threadIdx.x;
    float s = 0.f;
#pragma unroll
    for (int i = 0; i < 32; i++) s += g_psum[i * L + p];
    g_cinv[p] = 1.0f / s;
}
__global__ void k_smax_norm() {
    int idx = blockIdx.x * blockDim.x + threadIdx.x;
    int p = idx & (L - 1);
    int q = idx >> 12;
    g_F[(size_t)q * L + p] = g_F[(size_t)q * L + p] * g_mm[q] * g_cinv[p];
}

// -------------------------- final scatter ----------------------------------
__global__ void k_scatter(float* __restrict__ out) {
    int idx = blockIdx.x * blockDim.x + threadIdx.x;   // < CDIM*HW*HW
    int c = idx >> 14;
    int y = (idx >> 7) & 127;
    int x = idx & 127;
    int py1 = (y + 1) >> 1;
    int px1 = (x + 1) >> 1;
    float acc = 0.f;
#pragma unroll
    for (int t = 0; t < 2; t++) {
        int py = py1 - t;
        if ((unsigned)py >= 64) continue;
        int i = y + 1 - 2 * py;     // in [0,4)
#pragma unroll
        for (int s2 = 0; s2 < 2; s2++) {
            int px = px1 - s2;
            if ((unsigned)px >= 64) continue;
            int j = x + 1 - 2 * px;
            acc += g_OP[(size_t)(py * 64 + px) * MP + c * 16 + i * 4 + j];
        }
    }
    out[idx] = acc * 0.25f;
}

// -------------------------- launch ------------------------------------------
extern "C" void kernel_launch(void* const* d_in, const int* in_sizes, int n_in,
                              void* d_out, int out_size) {
    (void)in_sizes; (void)n_in; (void)out_size;
    const float* f    = (const float*)d_in[0];
    const float* b    = (const float*)d_in[1];
    const float* mask = (const float*)d_in[2];
    float* out = (float*)d_out;

    k_mm<<<16, 256>>>(mask);

    for (int bi = 0; bi < 2; bi++) {
        const float* fb = f + (size_t)bi * BSTRIDE;
        const float* bb = b + (size_t)bi * BSTRIDE;

        k_norm<<<L, 128>>>(bb);
        k_build<<<(KP * L) / 256, 256>>>(fb, bb);
        k_buildRW<<<(int)(((size_t)L * MP) / 256), 256>>>(bb);

        k_gemm<<<dim3(L / 128, L / 128), 256>>>(0);       // S = WnT^T PfT

        k_fuse<<<(int)(((size_t)L * L) / 256), 256>>>();

        k_smax_max<<<dim3(L / 256, 32), 256>>>();
        k_rmax<<<L / 256, 256>>>();
        k_smax_sum<<<dim3(L / 256, 32), 256>>>();
        k_rsum<<<L / 256, 256>>>();
        k_smax_norm<<<(int)(((size_t)L * L) / 256), 256>>>();

        k_gemm<<<dim3(MP / 128, L / 128), 256>>>(1);      // OP = A^T RW

        k_scatter<<<(CDIM * HW * HW) / 256, 256>>>(out + (size_t)bi * BSTRIDE);
    }
}

// round 9
// speedup vs baseline: 1.0037x; 1.0010x over previous
#include <cuda_runtime.h>

// ---------------------------------------------------------------------------
// Contextual attention, decomposed:
//   GEMM1: S[q,p] = <wn_q, pf_p>          (4096 x 4096 x 1152)
//   Fuse : 9-tap diagonal gather via flat transpose
//   Softmax over q (columns), scale 10, mask gate mm[q]
//   GEMM2: OP[p,m] = sum_q A[q,p] RW[q,m] (4096 x 2048 x 4096)
//   Scatter: out[c,y,x] = 0.25 * sum of <=4 OP taps
// ---------------------------------------------------------------------------

#define CDIM 128
#define HW   128
#define HD   64
#define L    4096          // HD*HD
#define KP   1152          // CDIM*9
#define MP   2048          // CDIM*16
#define BSTRIDE (CDIM*HW*HW)

typedef unsigned long long u64;

// -------------------------- device scratch --------------------------------
__device__ float g_WnT[(size_t)KP * L];          // [k][q]
__device__ float g_PfT[(size_t)KP * L];          // [k][p]
__device__ float g_RW [(size_t)L  * MP];         // [q][m]
__device__ float g_S  [(size_t)L  * L];          // [q][p]
__device__ float g_F  [(size_t)L  * L];          // [q][p] fused, then softmaxed
__device__ float g_OP [(size_t)L  * MP];         // [p][m]
__device__ float g_norm_inv[L];
__device__ float g_mm[L];
__device__ float g_pmax[32 * L];
__device__ float g_psum[32 * L];
__device__ float g_cmax[L];
__device__ float g_cinv[L];

// -------------------------- small helpers ---------------------------------
__device__ __forceinline__ int tau_idx(int a) { return ((a & 63) << 6) | (a >> 6); }

__device__ __forceinline__ u64 pack2(float lo, float hi) {
    u64 r; asm("mov.b64 %0, {%1, %2};" : "=l"(r) : "f"(lo), "f"(hi)); return r;
}
__device__ __forceinline__ float2 unpack2(u64 v) {
    float2 r; asm("mov.b64 {%0, %1}, %2;" : "=f"(r.x), "=f"(r.y) : "l"(v)); return r;
}
__device__ __forceinline__ void fma2(u64& d, u64 a, u64 b) {
    asm("fma.rn.f32x2 %0, %1, %2, %0;" : "+l"(d) : "l"(a), "l"(b));
}

// -------------------------- mask gate --------------------------------------
__global__ void k_mm(const float* __restrict__ mask) {
    int q = blockIdx.x * blockDim.x + threadIdx.x;
    if (q >= L) return;
    int qy = q >> 6, qx = q & 63;
    float s = 0.f;
    for (int dy = -1; dy <= 1; dy++)
        for (int dx = -1; dx <= 1; dx++) {
            int yy = qy + dy, xx = qx + dx;
            if ((unsigned)yy < HD && (unsigned)xx < HD)
                s += mask[(2 * yy) * HW + 2 * xx];
        }
    g_mm[q] = (s == 0.0f) ? 1.0f : 0.0f;
}

// -------------------------- patch norms ------------------------------------
__global__ void k_norm(const float* __restrict__ b) {
    int q = blockIdx.x;
    int c = threadIdx.x;                 // 128 threads
    int qy = q >> 6, qx = q & 63;
    const float* bc = b + (size_t)c * HW * HW;
    float s = 0.f;
    for (int dy = -1; dy <= 1; dy++) {
        int yy = qy + dy; if ((unsigned)yy >= HD) continue;
        for (int dx = -1; dx <= 1; dx++) {
            int xx = qx + dx; if ((unsigned)xx >= HD) continue;
            float v = bc[(2 * yy) * HW + 2 * xx];
            s += v * v;
        }
    }
    __shared__ float sh[128];
    sh[c] = s; __syncthreads();
    for (int o = 64; o > 0; o >>= 1) {
        if (c < o) sh[c] += sh[c + o];
        __syncthreads();
    }
    if (c == 0) {
        float n = sqrtf(sh[0]);
        g_norm_inv[q] = 1.0f / fmaxf(n, 1e-4f);
    }
}

// -------------------- build PfT (f patches) & WnT (normalized b patches) ---
__global__ void k_build(const float* __restrict__ f, const float* __restrict__ b) {
    int idx = blockIdx.x * blockDim.x + threadIdx.x;
    if (idx >= KP * L) return;
    int q = idx & (L - 1);
    int k = idx >> 12;
    int c = k / 9;
    int r = k - 9 * c;
    int dy = r / 3 - 1, dx = r % 3 - 1;
    int qy = (q >> 6) + dy, qx = (q & 63) + dx;
    float fv = 0.f, bv = 0.f;
    if ((unsigned)qy < HD && (unsigned)qx < HD) {
        size_t off = (size_t)c * HW * HW + (size_t)(2 * qy) * HW + 2 * qx;
        fv = f[off]; bv = b[off];
    }
    g_PfT[idx] = fv;
    g_WnT[idx] = bv * g_norm_inv[q];
}

// -------------------- build RW (raw 4x4 stride-2 patches of full-res b) ----
__global__ void k_buildRW(const float* __restrict__ b) {
    size_t idx = (size_t)blockIdx.x * blockDim.x + threadIdx.x;
    if (idx >= (size_t)L * MP) return;
    int m = (int)(idx & (MP - 1));
    int q = (int)(idx >> 11);
    int c = m >> 4, i = (m >> 2) & 3, j = m & 3;
    int y = 2 * (q >> 6) - 1 + i;
    int x = 2 * (q & 63) - 1 + j;
    float v = 0.f;
    if ((unsigned)y < HW && (unsigned)x < HW)
        v = b[(size_t)c * HW * HW + (size_t)y * HW + x];
    g_RW[idx] = v;
}

// -------------------------- SGEMM (TN, fp32x2 FFMA2) -----------------------
// C[M,N] = sum_k A[k][m] * B[k][n];  BM=BN=128, BK=8, 256 thr, 8x8 microtile
__global__ __launch_bounds__(256) void k_gemm(int which) {
    const float* __restrict__ A;
    const float* __restrict__ B;
    float* __restrict__ C;
    int N, K;
    if (which == 0) { A = g_WnT; B = g_PfT; C = g_S;  N = L;  K = KP; }
    else            { A = g_F;   B = g_RW;  C = g_OP; N = MP; K = L;  }
    const int M = L;

    __shared__ __align__(16) float As[8][128];
    __shared__ __align__(16) float Bs[8][128];

    int bm = blockIdx.y * 128, bn = blockIdx.x * 128;
    int tid = threadIdx.x;
    int lr = tid >> 5;
    int lc = (tid & 31) << 2;
    int tm = (tid >> 4) << 3;
    int tn = (tid & 15) << 3;

    const float* Ag = A + (size_t)lr * M + bm + lc;
    const float* Bg = B + (size_t)lr * N + bn + lc;
    float4 ra = *(const float4*)Ag;
    float4 rb = *(const float4*)Bg;

    u64 acc2[8][4];
#pragma unroll
    for (int i = 0; i < 8; i++)
#pragma unroll
        for (int j = 0; j < 4; j++) acc2[i][j] = 0ull;

    int kiter = K >> 3;
    for (int t = 0; t < kiter; t++) {
        *(float4*)&As[lr][lc] = ra;
        *(float4*)&Bs[lr][lc] = rb;
        __syncthreads();
        if (t + 1 < kiter) {
            Ag += 8 * (size_t)M; Bg += 8 * (size_t)N;
            ra = *(const float4*)Ag;
            rb = *(const float4*)Bg;
        }
#pragma unroll
        for (int kk = 0; kk < 8; kk++) {
            float4 a0 = *(const float4*)&As[kk][tm];
            float4 a1 = *(const float4*)&As[kk][tm + 4];
            float4 b0 = *(const float4*)&Bs[kk][tn];
            float4 b1 = *(const float4*)&Bs[kk][tn + 4];
            u64 bv0 = pack2(b0.x, b0.y), bv1 = pack2(b0.z, b0.w);
            u64 bv2 = pack2(b1.x, b1.y), bv3 = pack2(b1.z, b1.w);
            float av[8] = {a0.x, a0.y, a0.z, a0.w, a1.x, a1.y, a1.z, a1.w};
#pragma unroll
            for (int i = 0; i < 8; i++) {
                u64 aa = pack2(av[i], av[i]);
                fma2(acc2[i][0], aa, bv0);
                fma2(acc2[i][1], aa, bv1);
                fma2(acc2[i][2], aa, bv2);
                fma2(acc2[i][3], aa, bv3);
            }
        }
        __syncthreads();
    }

#pragma unroll
    for (int i = 0; i < 8; i++) {
        float2 v0 = unpack2(acc2[i][0]);
        float2 v1 = unpack2(acc2[i][1]);
        float2 v2 = unpack2(acc2[i][2]);
        float2 v3 = unpack2(acc2[i][3]);
        float4 o0 = make_float4(v0.x, v0.y, v1.x, v1.y);
        float4 o1 = make_float4(v2.x, v2.y, v3.x, v3.y);
        size_t row = (size_t)(bm + tm + i) * N + (bn + tn);
        *(float4*)&C[row]     = o0;
        *(float4*)&C[row + 4] = o1;
    }
}

// -------------------------- fuse (two eye(3) convs + transposes) -----------
__global__ void k_fuse() {
    int idx = blockIdx.x * blockDim.x + threadIdx.x;   // < L*L = 16.7M
    int p = idx & (L - 1);
    int q = idx >> 12;
    int tq = tau_idx(q), tp = tau_idx(p);
    float acc = 0.f;
#pragma unroll
    for (int d2 = -1; d2 <= 1; d2++) {
        int aq = tq + d2, ap = tp + d2;
        if ((unsigned)aq < L && (unsigned)ap < L) {
            int uq = tau_idx(aq), up = tau_idx(ap);
#pragma unroll
            for (int d1 = -1; d1 <= 1; d1++) {
                int vq = uq + d1, vp = up + d1;
                if ((unsigned)vq < L && (unsigned)vp < L)
                    acc += g_S[(size_t)vq * L + vp];
            }
        }
    }
    g_F[(size_t)q * L + p] = acc;
}

// -------------------------- softmax over q (split along q) -----------------
__global__ void k_smax_max() {
    int p = blockIdx.x * blockDim.x + threadIdx.x;     // grid.x = 16
    int q0 = blockIdx.y * 128;                          // grid.y = 32
    float m = -1e30f;
#pragma unroll 4
    for (int q = q0; q < q0 + 128; q++) {
        float v = g_F[(size_t)q * L + p] * g_mm[q] * 10.0f;
        m = fmaxf(m, v);
    }
    g_pmax[blockIdx.y * L + p] = m;
}
__global__ void k_rmax() {
    int p = blockIdx.x * blockDim.x + threadIdx.x;
    float m = -1e30f;
#pragma unroll
    for (int i = 0; i < 32; i++) m = fmaxf(m, g_pmax[i * L + p]);
    g_cmax[p] = m;
}
__global__ void k_smax_sum() {
    int p = blockIdx.x * blockDim.x + threadIdx.x;
    int q0 = blockIdx.y * 128;
    float m = g_cmax[p];
    float s = 0.f;
#pragma unroll 4
    for (int q = q0; q < q0 + 128; q++) {
        float v = g_F[(size_t)q * L + p] * g_mm[q] * 10.0f;
        float e = expf(v - m);
        s += e;
        g_F[(size_t)q * L + p] = e;
    }
    g_psum[blockIdx.y * L + p] = s;
}
__global__ void k_rsum() {
    int p = blockIdx.x * blockDim.x + threadIdx.x;
    float s = 0.f;
#pragma unroll
    for (int i = 0; i < 32; i++) s += g_psum[i * L + p];
    g_cinv[p] = 1.0f / s;
}
__global__ void k_smax_norm() {
    int idx = blockIdx.x * blockDim.x + threadIdx.x;
    int p = idx & (L - 1);
    int q = idx >> 12;
    g_F[(size_t)q * L + p] = g_F[(size_t)q * L + p] * g_mm[q] * g_cinv[p];
}

// -------------------------- final scatter ----------------------------------
__global__ void k_scatter(float* __restrict__ out) {
    int idx = blockIdx.x * blockDim.x + threadIdx.x;   // < CDIM*HW*HW
    int c = idx >> 14;
    int y = (idx >> 7) & 127;
    int x = idx & 127;
    int py1 = (y + 1) >> 1;
    int px1 = (x + 1) >> 1;
    float acc = 0.f;
#pragma unroll
    for (int t = 0; t < 2; t++) {
        int py = py1 - t;
        if ((unsigned)py >= 64) continue;
        int i = y + 1 - 2 * py;     // in [0,4)
#pragma unroll
        for (int s2 = 0; s2 < 2; s2++) {
            int px = px1 - s2;
            if ((unsigned)px >= 64) continue;
            int j = x + 1 - 2 * px;
            acc += g_OP[(size_t)(py * 64 + px) * MP + c * 16 + i * 4 + j];
        }
    }
    out[idx] = acc * 0.25f;
}

// -------------------------- launch ------------------------------------------
extern "C" void kernel_launch(void* const* d_in, const int* in_sizes, int n_in,
                              void* d_out, int out_size) {
    (void)in_sizes; (void)n_in; (void)out_size;
    const float* f    = (const float*)d_in[0];
    const float* b    = (const float*)d_in[1];
    const float* mask = (const float*)d_in[2];
    float* out = (float*)d_out;

    k_mm<<<16, 256>>>(mask);

    for (int bi = 0; bi < 2; bi++) {
        const float* fb = f + (size_t)bi * BSTRIDE;
        const float* bb = b + (size_t)bi * BSTRIDE;

        k_norm<<<L, 128>>>(bb);
        k_build<<<(KP * L) / 256, 256>>>(fb, bb);
        k_buildRW<<<(int)(((size_t)L * MP) / 256), 256>>>(bb);

        k_gemm<<<dim3(L / 128, L / 128), 256>>>(0);       // S = WnT^T PfT

        k_fuse<<<(int)(((size_t)L * L) / 256), 256>>>();

        k_smax_max<<<dim3(L / 256, 32), 256>>>();
        k_rmax<<<L / 256, 256>>>();
        k_smax_sum<<<dim3(L / 256, 32), 256>>>();
        k_rsum<<<L / 256, 256>>>();
        k_smax_norm<<<(int)(((size_t)L * L) / 256), 256>>>();

        k_gemm<<<dim3(MP / 128, L / 128), 256>>>(1);      // OP = A^T RW

        k_scatter<<<(CDIM * HW * HW) / 256, 256>>>(out + (size_t)bi * BSTRIDE);
    }
}